// round 8
// baseline (speedup 1.0000x reference)
#include <cuda_runtime.h>

#define NB      4
#define P       8192
#define NPTS    (NB * P)            // 32768
#define NBIN1   64
#define NBINS   (NBIN1 * NBIN1)     // 4096 per batch
#define GBINS   (NB * NBINS)        // 16384
#define XMIN    (-5.0f)
#define BINW    0.15625f            // 10 / 64
#define INVW    6.4f
#define NEG_INF (-3.402823466e38f)

#define SUM_TPB  256
#define SUM_BLKS (NPTS / SUM_TPB)   // 128

__device__ int    d_tcnt[GBINS], d_toff[GBINS], d_tcur[GBINS];
__device__ int    d_scnt[GBINS], d_soff[GBINS], d_scur[GBINS];
__device__ float4 d_tp[NPTS];       // sorted targets: (x, y, z, -0.5*|t|^2)
__device__ float4 d_sp[NPTS];       // sorted sources: (x, y, z, bitcast(orig idx))
__device__ float  g_nn[NPTS];       // nn_d2 by ORIGINAL source index (deterministic)
__device__ float  g_part[SUM_BLKS];

__device__ __forceinline__ int clampi(int v, int lo, int hi) {
    return v < lo ? lo : (v > hi ? hi : v);
}
__device__ __forceinline__ int bin2d(float x, float y) {
    int bx = clampi((int)((x - XMIN) * INVW), 0, NBIN1 - 1);
    int by = clampi((int)((y - XMIN) * INVW), 0, NBIN1 - 1);
    return by * NBIN1 + bx;
}

// ---------------- K1: clear counts/cursors ----------------
__global__ void k_clear() {
    int i = blockIdx.x * blockDim.x + threadIdx.x;
    if (i < GBINS) { d_tcnt[i] = 0; d_tcur[i] = 0; d_scnt[i] = 0; d_scur[i] = 0; }
}

// ---------------- K2: histogram ----------------
__global__ void k_count(const float* __restrict__ src, const float* __restrict__ tgt) {
    int i = blockIdx.x * blockDim.x + threadIdx.x;   // 0..2*NPTS-1
    if (i < NPTS) {
        const float* t = tgt + (long)i * 3;
        int b = i / P;
        atomicAdd(&d_tcnt[b * NBINS + bin2d(t[0], t[1])], 1);
    } else {
        int j = i - NPTS;
        const float* s = src + (long)j * 3;
        int b = j / P;
        atomicAdd(&d_scnt[b * NBINS + bin2d(s[0], s[1])], 1);
    }
}

// ---------------- K3: exclusive prefix scan over GBINS (2 blocks: tgt, src) ----------------
__global__ __launch_bounds__(1024) void k_scan() {
    __shared__ int sm[1024];
    __shared__ int carry;
    const int tid = threadIdx.x;
    const int* cnt = (blockIdx.x == 0) ? d_tcnt : d_scnt;
    int*       off = (blockIdx.x == 0) ? d_toff : d_soff;
    if (tid == 0) carry = 0;
    __syncthreads();
    for (int c = 0; c < GBINS / 1024; c++) {
        int idx = c * 1024 + tid;
        int v = cnt[idx];
        sm[tid] = v;
        __syncthreads();
        #pragma unroll
        for (int d = 1; d < 1024; d <<= 1) {
            int t = (tid >= d) ? sm[tid - d] : 0;
            __syncthreads();
            sm[tid] += t;
            __syncthreads();
        }
        off[idx] = carry + sm[tid] - v;       // exclusive
        int tot = sm[1023];
        __syncthreads();
        if (tid == 0) carry += tot;
        __syncthreads();
    }
}

// ---------------- K4: scatter into sorted order ----------------
__global__ void k_scatter(const float* __restrict__ src, const float* __restrict__ tgt) {
    int i = blockIdx.x * blockDim.x + threadIdx.x;
    if (i < NPTS) {
        const float* t = tgt + (long)i * 3;
        float x = t[0], y = t[1], z = t[2];
        int b = i / P;
        int g = b * NBINS + bin2d(x, y);
        int pos = d_toff[g] + atomicAdd(&d_tcur[g], 1);
        d_tp[pos] = make_float4(x, y, z, -0.5f * (x * x + y * y + z * z));
    } else {
        int j = i - NPTS;
        const float* s = src + (long)j * 3;
        float x = s[0], y = s[1], z = s[2];
        int b = j / P;
        int g = b * NBINS + bin2d(x, y);
        int pos = d_soff[g] + atomicAdd(&d_scur[g], 1);
        d_sp[pos] = make_float4(x, y, z, __int_as_float(j));
    }
}

// ---------------- K5: ring search (exact NN) ----------------
__global__ __launch_bounds__(128) void k_search() {
    const int slot = blockIdx.x * 128 + threadIdx.x;  // sorted slot; batch-major
    float4 s = d_sp[slot];
    const float sx = s.x, sy = s.y, sz = s.z;
    const int   idx = __float_as_int(s.w);
    const float s2 = sx * sx + sy * sy + sz * sz;
    const int batch = slot / P;
    const int base  = batch * NBINS;
    const int bx = clampi((int)((sx - XMIN) * INVW), 0, NBIN1 - 1);
    const int by = clampi((int)((sy - XMIN) * INVW), 0, NBIN1 - 1);

    float m = NEG_INF;   // max over targets of (s.t - 0.5|t|^2)

    // scan one bin
    #define SCANBIN(G) do {                                                     \
        int _g = (G);                                                           \
        int _o = d_toff[_g], _n = d_tcnt[_g];                                   \
        for (int _k = 0; _k < _n; _k++) {                                       \
            float4 _t = d_tp[_o + _k];                                          \
            m = fmaxf(m, fmaf(sx, _t.x, fmaf(sy, _t.y, fmaf(sz, _t.z, _t.w)))); \
        }                                                                       \
    } while (0)

    for (int r = 0; r < NBIN1; r++) {
        if (r > 0) {
            // any point in an unscanned bin (Chebyshev ring >= r) is >= (r-1)*BINW away
            float lb = (float)(r - 1) * BINW;
            float d2b = fmaf(-2.0f, m, s2);       // +inf while m == -inf
            if (lb * lb >= d2b) break;
        }
        if (r == 0) {
            SCANBIN(base + by * NBIN1 + bx);
        } else {
            int x0 = bx - r, x1 = bx + r, y0 = by - r, y1 = by + r;
            int cx0 = x0 < 0 ? 0 : x0;
            int cx1 = x1 > NBIN1 - 1 ? NBIN1 - 1 : x1;
            if (y0 >= 0)      for (int b = cx0; b <= cx1; b++) SCANBIN(base + y0 * NBIN1 + b);
            if (y1 < NBIN1)   for (int b = cx0; b <= cx1; b++) SCANBIN(base + y1 * NBIN1 + b);
            int cy0 = (y0 + 1) < 0 ? 0 : (y0 + 1);
            int cy1 = (y1 - 1) > NBIN1 - 1 ? NBIN1 - 1 : (y1 - 1);
            if (x0 >= 0)      for (int b = cy0; b <= cy1; b++) SCANBIN(base + b * NBIN1 + x0);
            if (x1 < NBIN1)   for (int b = cy0; b <= cy1; b++) SCANBIN(base + b * NBIN1 + x1);
        }
    }
    #undef SCANBIN

    g_nn[idx] = fmaxf(0.0f, fmaf(-2.0f, m, s2));
}

// ---------------- K6: deterministic fixed-order sum ----------------
__global__ __launch_bounds__(SUM_TPB) void k_sum1() {
    __shared__ float red[SUM_TPB];
    const int tid = threadIdx.x;
    red[tid] = g_nn[blockIdx.x * SUM_TPB + tid];
    __syncthreads();
    #pragma unroll
    for (int st = SUM_TPB / 2; st > 0; st >>= 1) {
        if (tid < st) red[tid] += red[tid + st];
        __syncthreads();
    }
    if (tid == 0) g_part[blockIdx.x] = red[0];
}

__global__ __launch_bounds__(SUM_BLKS) void k_sum2(float* __restrict__ out) {
    __shared__ float red[SUM_BLKS];
    const int tid = threadIdx.x;
    red[tid] = g_part[tid];
    __syncthreads();
    #pragma unroll
    for (int st = SUM_BLKS / 2; st > 0; st >>= 1) {
        if (tid < st) red[tid] += red[tid + st];
        __syncthreads();
    }
    if (tid == 0) out[0] = red[0] * (1.0f / (float)NB);
}

extern "C" void kernel_launch(void* const* d_in, const int* in_sizes, int n_in,
                              void* d_out, int out_size) {
    const float* src = (const float*)d_in[0];   // (4, 8192, 3) f32
    const float* tgt = (const float*)d_in[1];   // (4, 8192, 3) f32
    float* out = (float*)d_out;                  // scalar f32

    k_clear  <<<(GBINS + 255) / 256, 256>>>();
    k_count  <<<(2 * NPTS) / 256, 256>>>(src, tgt);
    k_scan   <<<2, 1024>>>();
    k_scatter<<<(2 * NPTS) / 256, 256>>>(src, tgt);
    k_search <<<NPTS / 128, 128>>>();
    k_sum1   <<<SUM_BLKS, SUM_TPB>>>();
    k_sum2   <<<1, SUM_BLKS>>>(out);
}

// round 9
// speedup vs baseline: 1.4933x; 1.4933x over previous
#include <cuda_runtime.h>

#define NB      4
#define P       8192
#define NPTS    (NB * P)            // 32768
#define NBIN1   64
#define NBINS   (NBIN1 * NBIN1)     // 4096 per batch
#define GBINS   (NB * NBINS)        // 16384
#define XMIN    (-5.0f)
#define BINW    0.15625f            // 10 / 64
#define INVW    6.4f
#define NEG_INF (-3.402823466e38f)

#define SUM_TPB  256
#define SUM_BLKS (NPTS / SUM_TPB)   // 128
#define SCAN_TPB 1024
#define BPT      (GBINS / SCAN_TPB) // 16 bins per scan-thread

__device__ int    d_tcnt[GBINS], d_scnt[GBINS];
__device__ int    d_tcur[GBINS], d_scur[GBINS];
__device__ int2   d_tbin[GBINS];    // (off, cnt) packed for one-LDG.64 bin fetch
__device__ float4 d_tp[NPTS];       // sorted targets: (x, y, z, -0.5*|t|^2)
__device__ float4 d_sp[NPTS];       // sorted sources: (x, y, z, bitcast(orig idx))
__device__ float  g_nn[NPTS];       // nn_d2 by ORIGINAL source index
__device__ float  g_part[SUM_BLKS];

__device__ __forceinline__ int clampi(int v, int lo, int hi) {
    return v < lo ? lo : (v > hi ? hi : v);
}
__device__ __forceinline__ int bin2d(float x, float y) {
    int bx = clampi((int)((x - XMIN) * INVW), 0, NBIN1 - 1);
    int by = clampi((int)((y - XMIN) * INVW), 0, NBIN1 - 1);
    return by * NBIN1 + bx;
}

// ---------------- K1: clear counts ----------------
__global__ void k_clear() {
    int i = blockIdx.x * blockDim.x + threadIdx.x;
    if (i < GBINS) { d_tcnt[i] = 0; d_scnt[i] = 0; }
}

// ---------------- K2: histogram ----------------
__global__ void k_count(const float* __restrict__ src, const float* __restrict__ tgt) {
    int i = blockIdx.x * blockDim.x + threadIdx.x;   // 0..2*NPTS-1
    if (i < NPTS) {
        const float* t = tgt + (long)i * 3;
        int b = i / P;
        atomicAdd(&d_tcnt[b * NBINS + bin2d(t[0], t[1])], 1);
    } else {
        int j = i - NPTS;
        const float* s = src + (long)j * 3;
        int b = j / P;
        atomicAdd(&d_scnt[b * NBINS + bin2d(s[0], s[1])], 1);
    }
}

// ---------------- K3: shuffle-scan alloc (block 0: targets, block 1: sources) ----------------
__global__ __launch_bounds__(SCAN_TPB) void k_alloc() {
    __shared__ int warp_tot[32];
    const int tid  = threadIdx.x;
    const int lane = tid & 31, wid = tid >> 5;
    const bool is_t = (blockIdx.x == 0);
    const int* cnt = is_t ? d_tcnt : d_scnt;

    int local[BPT];
    int sum = 0;
    const int b0 = tid * BPT;
    #pragma unroll
    for (int j = 0; j < BPT; j++) { local[j] = cnt[b0 + j]; sum += local[j]; }

    // warp-inclusive scan of per-thread sums
    int inc = sum;
    #pragma unroll
    for (int d = 1; d < 32; d <<= 1) {
        int v = __shfl_up_sync(0xffffffffu, inc, d);
        if (lane >= d) inc += v;
    }
    if (lane == 31) warp_tot[wid] = inc;
    __syncthreads();
    if (wid == 0) {
        int v = warp_tot[lane];
        int iv = v;
        #pragma unroll
        for (int d = 1; d < 32; d <<= 1) {
            int u = __shfl_up_sync(0xffffffffu, iv, d);
            if (lane >= d) iv += u;
        }
        warp_tot[lane] = iv - v;          // exclusive warp base
    }
    __syncthreads();

    int base = warp_tot[wid] + (inc - sum);  // exclusive offset of this thread's first bin
    #pragma unroll
    for (int j = 0; j < BPT; j++) {
        int g = b0 + j;
        if (is_t) { d_tbin[g] = make_int2(base, local[j]); d_tcur[g] = base; }
        else      { d_scur[g] = base; }
        base += local[j];
    }
}

// ---------------- K4: scatter into sorted order ----------------
__global__ void k_scatter(const float* __restrict__ src, const float* __restrict__ tgt) {
    int i = blockIdx.x * blockDim.x + threadIdx.x;
    if (i < NPTS) {
        const float* t = tgt + (long)i * 3;
        float x = t[0], y = t[1], z = t[2];
        int b = i / P;
        int g = b * NBINS + bin2d(x, y);
        int pos = atomicAdd(&d_tcur[g], 1);
        d_tp[pos] = make_float4(x, y, z, -0.5f * (x * x + y * y + z * z));
    } else {
        int j = i - NPTS;
        const float* s = src + (long)j * 3;
        float x = s[0], y = s[1], z = s[2];
        int b = j / P;
        int g = b * NBINS + bin2d(x, y);
        int pos = atomicAdd(&d_scur[g], 1);
        d_sp[pos] = make_float4(x, y, z, __int_as_float(j));
    }
}

// ---------------- K5: warp-per-source ring search (exact NN) ----------------
__global__ __launch_bounds__(256) void k_search() {
    const int w    = blockIdx.x * 8 + (threadIdx.x >> 5);  // source slot (sorted)
    const int lane = threadIdx.x & 31;

    float4 s = d_sp[w];
    const float sx = s.x, sy = s.y, sz = s.z;
    const int   idx = __float_as_int(s.w);
    const float s2 = sx * sx + sy * sy + sz * sz;
    const int batch = w / P;
    const int base  = batch * NBINS;
    const int bx = clampi((int)((sx - XMIN) * INVW), 0, NBIN1 - 1);
    const int by = clampi((int)((sy - XMIN) * INVW), 0, NBIN1 - 1);

    float m     = NEG_INF;   // per-lane partial max of (s.t - 0.5|t|^2)
    float m_all = NEG_INF;   // warp-wide max (valid after each ring)

    // lanes stride coalesced over points in one bin
    #define SCANBIN(G) do {                                                     \
        int2 _oc = d_tbin[(G)];                                                 \
        for (int _k = lane; _k < _oc.y; _k += 32) {                             \
            float4 _t = d_tp[_oc.x + _k];                                       \
            m = fmaxf(m, fmaf(sx, _t.x, fmaf(sy, _t.y, fmaf(sz, _t.z, _t.w)))); \
        }                                                                       \
    } while (0)

    for (int r = 0; r < NBIN1; r++) {
        if (r > 0) {
            // any point in an unscanned bin (Chebyshev ring >= r) is >= (r-1)*BINW away
            float lb = (float)(r - 1) * BINW;
            if (lb * lb >= fmaf(-2.0f, m_all, s2)) break;   // warp-uniform
        }
        if (r == 0) {
            SCANBIN(base + by * NBIN1 + bx);
        } else {
            int x0 = bx - r, x1 = bx + r, y0 = by - r, y1 = by + r;
            int cx0 = x0 < 0 ? 0 : x0;
            int cx1 = x1 > NBIN1 - 1 ? NBIN1 - 1 : x1;
            if (y0 >= 0)      for (int b = cx0; b <= cx1; b++) SCANBIN(base + y0 * NBIN1 + b);
            if (y1 < NBIN1)   for (int b = cx0; b <= cx1; b++) SCANBIN(base + y1 * NBIN1 + b);
            int cy0 = (y0 + 1) < 0 ? 0 : (y0 + 1);
            int cy1 = (y1 - 1) > NBIN1 - 1 ? NBIN1 - 1 : (y1 - 1);
            if (x0 >= 0)      for (int b = cy0; b <= cy1; b++) SCANBIN(base + b * NBIN1 + x0);
            if (x1 < NBIN1)   for (int b = cy0; b <= cy1; b++) SCANBIN(base + b * NBIN1 + x1);
        }
        // warp-wide max (max is order-independent -> deterministic result)
        float mm = m;
        #pragma unroll
        for (int o = 16; o; o >>= 1)
            mm = fmaxf(mm, __shfl_xor_sync(0xffffffffu, mm, o));
        m_all = mm;
    }
    #undef SCANBIN

    if (lane == 0)
        g_nn[idx] = fmaxf(0.0f, fmaf(-2.0f, m_all, s2));
}

// ---------------- K6: deterministic fixed-order sum ----------------
__global__ __launch_bounds__(SUM_TPB) void k_sum1() {
    __shared__ float red[SUM_TPB];
    const int tid = threadIdx.x;
    red[tid] = g_nn[blockIdx.x * SUM_TPB + tid];
    __syncthreads();
    #pragma unroll
    for (int st = SUM_TPB / 2; st > 0; st >>= 1) {
        if (tid < st) red[tid] += red[tid + st];
        __syncthreads();
    }
    if (tid == 0) g_part[blockIdx.x] = red[0];
}

__global__ __launch_bounds__(SUM_BLKS) void k_sum2(float* __restrict__ out) {
    __shared__ float red[SUM_BLKS];
    const int tid = threadIdx.x;
    red[tid] = g_part[tid];
    __syncthreads();
    #pragma unroll
    for (int st = SUM_BLKS / 2; st > 0; st >>= 1) {
        if (tid < st) red[tid] += red[tid + st];
        __syncthreads();
    }
    if (tid == 0) out[0] = red[0] * (1.0f / (float)NB);
}

extern "C" void kernel_launch(void* const* d_in, const int* in_sizes, int n_in,
                              void* d_out, int out_size) {
    const float* src = (const float*)d_in[0];   // (4, 8192, 3) f32
    const float* tgt = (const float*)d_in[1];   // (4, 8192, 3) f32
    float* out = (float*)d_out;                  // scalar f32

    k_clear  <<<GBINS / 256, 256>>>();
    k_count  <<<(2 * NPTS) / 256, 256>>>(src, tgt);
    k_alloc  <<<2, SCAN_TPB>>>();
    k_scatter<<<(2 * NPTS) / 256, 256>>>(src, tgt);
    k_search <<<NPTS / 8, 256>>>();              // one warp per source
    k_sum1   <<<SUM_BLKS, SUM_TPB>>>();
    k_sum2   <<<1, SUM_BLKS>>>(out);
}

// round 10
// speedup vs baseline: 2.1149x; 1.4162x over previous
#include <cuda_runtime.h>

#define NB      4
#define P       8192
#define NPTS    (NB * P)            // 32768
#define NBIN1   64
#define NBINS   (NBIN1 * NBIN1)     // 4096 per batch
#define GBINS   (NB * NBINS)        // 16384
#define XMIN    (-5.0f)
#define BINW    0.15625f            // 10 / 64
#define INVW    6.4f
#define NEG_INF (-3.402823466e38f)

#define SUM_TPB  256
#define SUM_BLKS (NPTS / SUM_TPB)   // 128
#define SCAN_TPB 1024
#define BPT      (GBINS / SCAN_TPB) // 16 bins per scan-thread

__device__ int    d_tcnt[GBINS], d_scnt[GBINS];
__device__ int    d_toff[GBINS];
__device__ int    d_tcur[GBINS], d_scur[GBINS];
__device__ float4 d_tp[NPTS];       // sorted targets: (x, y, z, -0.5*|t|^2)
__device__ float4 d_sp[NPTS];       // sorted sources: (x, y, z, bitcast(orig idx))
__device__ float  g_nn[NPTS];       // nn_d2 by ORIGINAL source index
__device__ float  g_part[SUM_BLKS];

__device__ __forceinline__ int clampi(int v, int lo, int hi) {
    return v < lo ? lo : (v > hi ? hi : v);
}
__device__ __forceinline__ int bin2d(float x, float y) {
    int bx = clampi((int)((x - XMIN) * INVW), 0, NBIN1 - 1);
    int by = clampi((int)((y - XMIN) * INVW), 0, NBIN1 - 1);
    return by * NBIN1 + bx;
}

// ---------------- K1: clear counts ----------------
__global__ void k_clear() {
    int i = blockIdx.x * blockDim.x + threadIdx.x;
    if (i < GBINS) { d_tcnt[i] = 0; d_scnt[i] = 0; }
}

// ---------------- K2: histogram ----------------
__global__ void k_count(const float* __restrict__ src, const float* __restrict__ tgt) {
    int i = blockIdx.x * blockDim.x + threadIdx.x;   // 0..2*NPTS-1
    if (i < NPTS) {
        const float* t = tgt + (long)i * 3;
        int b = i / P;
        atomicAdd(&d_tcnt[b * NBINS + bin2d(t[0], t[1])], 1);
    } else {
        int j = i - NPTS;
        const float* s = src + (long)j * 3;
        int b = j / P;
        atomicAdd(&d_scnt[b * NBINS + bin2d(s[0], s[1])], 1);
    }
}

// ---------------- K3: shuffle-scan alloc (block 0: targets, block 1: sources) ----------------
__global__ __launch_bounds__(SCAN_TPB) void k_alloc() {
    __shared__ int warp_tot[32];
    const int tid  = threadIdx.x;
    const int lane = tid & 31, wid = tid >> 5;
    const bool is_t = (blockIdx.x == 0);
    const int* cnt = is_t ? d_tcnt : d_scnt;

    int local[BPT];
    int sum = 0;
    const int b0 = tid * BPT;
    #pragma unroll
    for (int j = 0; j < BPT; j++) { local[j] = cnt[b0 + j]; sum += local[j]; }

    int inc = sum;
    #pragma unroll
    for (int d = 1; d < 32; d <<= 1) {
        int v = __shfl_up_sync(0xffffffffu, inc, d);
        if (lane >= d) inc += v;
    }
    if (lane == 31) warp_tot[wid] = inc;
    __syncthreads();
    if (wid == 0) {
        int v = warp_tot[lane];
        int iv = v;
        #pragma unroll
        for (int d = 1; d < 32; d <<= 1) {
            int u = __shfl_up_sync(0xffffffffu, iv, d);
            if (lane >= d) iv += u;
        }
        warp_tot[lane] = iv - v;
    }
    __syncthreads();

    int base = warp_tot[wid] + (inc - sum);  // exclusive offset of this thread's first bin
    #pragma unroll
    for (int j = 0; j < BPT; j++) {
        int g = b0 + j;
        if (is_t) { d_toff[g] = base; d_tcur[g] = base; }
        else      { d_scur[g] = base; }
        base += local[j];
    }
}

// ---------------- K4: scatter into sorted order ----------------
__global__ void k_scatter(const float* __restrict__ src, const float* __restrict__ tgt) {
    int i = blockIdx.x * blockDim.x + threadIdx.x;
    if (i < NPTS) {
        const float* t = tgt + (long)i * 3;
        float x = t[0], y = t[1], z = t[2];
        int b = i / P;
        int g = b * NBINS + bin2d(x, y);
        int pos = atomicAdd(&d_tcur[g], 1);
        d_tp[pos] = make_float4(x, y, z, -0.5f * (x * x + y * y + z * z));
    } else {
        int j = i - NPTS;
        const float* s = src + (long)j * 3;
        float x = s[0], y = s[1], z = s[2];
        int b = j / P;
        int g = b * NBINS + bin2d(x, y);
        int pos = atomicAdd(&d_scur[g], 1);
        d_sp[pos] = make_float4(x, y, z, __int_as_float(j));
    }
}

// ---------------- K5: warp-per-source, row-segment square search (exact NN) ----------------
__device__ __forceinline__ float warp_max(float v) {
    #pragma unroll
    for (int o = 16; o; o >>= 1)
        v = fmaxf(v, __shfl_xor_sync(0xffffffffu, v, o));
    return v;
}

__global__ __launch_bounds__(256) void k_search() {
    const int w    = blockIdx.x * 8 + (threadIdx.x >> 5);  // source slot (sorted)
    const int lane = threadIdx.x & 31;

    float4 s = d_sp[w];
    const float sx = s.x, sy = s.y, sz = s.z;
    const int   idx = __float_as_int(s.w);
    const float s2 = sx * sx + sy * sy + sz * sz;
    const int batch = w / P;
    const int base  = batch * NBINS;
    const int bx = clampi((int)((sx - XMIN) * INVW), 0, NBIN1 - 1);
    const int by = clampi((int)((sy - XMIN) * INVW), 0, NBIN1 - 1);

    float m = NEG_INF;   // per-lane partial max of (s.t - 0.5*|t|^2)

    // scan full square of Chebyshev radius R: one contiguous range per row
    #define SCANSQ(R) do {                                                      \
        int _y0 = clampi(by - (R), 0, NBIN1 - 1);                               \
        int _y1 = clampi(by + (R), 0, NBIN1 - 1);                               \
        int _x0 = clampi(bx - (R), 0, NBIN1 - 1);                               \
        int _x1 = clampi(bx + (R), 0, NBIN1 - 1);                               \
        for (int _y = _y0; _y <= _y1; _y++) {                                   \
            int _g0 = base + _y * NBIN1 + _x0;                                  \
            int _g1 = base + _y * NBIN1 + _x1;                                  \
            int _off = d_toff[_g0];                                             \
            int _end = d_toff[_g1] + d_tcnt[_g1];                               \
            for (int _k = _off + lane; _k < _end; _k += 32) {                   \
                float4 _t = d_tp[_k];                                           \
                m = fmaxf(m, fmaf(sx, _t.x, fmaf(sy, _t.y, fmaf(sz, _t.z, _t.w)))); \
            }                                                                   \
        }                                                                       \
    } while (0)

    // Phase 1: 3x3 core (3 row-segments)
    SCANSQ(1);
    float mm = warp_max(m);
    int Rdone = 1;
    // Rare: empty core -> double until a point is found (rescans are idempotent under max)
    while (mm == NEG_INF && Rdone < NBIN1) {
        Rdone *= 2;
        SCANSQ(Rdone);
        mm = warp_max(m);
    }

    // Phase 2: required radius from the bound; any unscanned bin (Chebyshev >= R+1)
    // holds points >= R*BINW away.
    float d2 = fmaxf(0.0f, fmaf(-2.0f, mm, s2));
    int Rneed = (int)(sqrtf(d2) * INVW) + 1;   // conservative ceil
    if (Rneed > Rdone && Rdone < NBIN1) {
        SCANSQ(Rneed);                          // full square incl. redundant core
        mm = warp_max(m);
    }
    #undef SCANSQ

    if (lane == 0)
        g_nn[idx] = fmaxf(0.0f, fmaf(-2.0f, mm, s2));
}

// ---------------- K6: deterministic fixed-order sum ----------------
__global__ __launch_bounds__(SUM_TPB) void k_sum1() {
    __shared__ float red[SUM_TPB];
    const int tid = threadIdx.x;
    red[tid] = g_nn[blockIdx.x * SUM_TPB + tid];
    __syncthreads();
    #pragma unroll
    for (int st = SUM_TPB / 2; st > 0; st >>= 1) {
        if (tid < st) red[tid] += red[tid + st];
        __syncthreads();
    }
    if (tid == 0) g_part[blockIdx.x] = red[0];
}

__global__ __launch_bounds__(SUM_BLKS) void k_sum2(float* __restrict__ out) {
    __shared__ float red[SUM_BLKS];
    const int tid = threadIdx.x;
    red[tid] = g_part[tid];
    __syncthreads();
    #pragma unroll
    for (int st = SUM_BLKS / 2; st > 0; st >>= 1) {
        if (tid < st) red[tid] += red[tid + st];
        __syncthreads();
    }
    if (tid == 0) out[0] = red[0] * (1.0f / (float)NB);
}

extern "C" void kernel_launch(void* const* d_in, const int* in_sizes, int n_in,
                              void* d_out, int out_size) {
    const float* src = (const float*)d_in[0];   // (4, 8192, 3) f32
    const float* tgt = (const float*)d_in[1];   // (4, 8192, 3) f32
    float* out = (float*)d_out;                  // scalar f32

    k_clear  <<<GBINS / 256, 256>>>();
    k_count  <<<(2 * NPTS) / 256, 256>>>(src, tgt);
    k_alloc  <<<2, SCAN_TPB>>>();
    k_scatter<<<(2 * NPTS) / 256, 256>>>(src, tgt);
    k_search <<<NPTS / 8, 256>>>();              // one warp per source
    k_sum1   <<<SUM_BLKS, SUM_TPB>>>();
    k_sum2   <<<1, SUM_BLKS>>>(out);
}